// round 2
// baseline (speedup 1.0000x reference)
#include <cuda_runtime.h>
#include <cstdint>
#include <cstddef>

#define B_     64
#define T_     512
#define D_     1024
#define U_     1024
#define L_     16
#define G_     4128
#define GP_    4224
#define NUB_   128          // unit blocks
#define NB_    129          // + 1 master block
#define MR_    32768        // B_*T_

// ---------------- static device scratch (no allocation APIs) ----------------
__device__ float    g_wp[(size_t)D_ * GP_];       // padded, tf32-rounded W
__device__ float    g_bp[GP_];                    // padded bias
__device__ float    g_xk[(size_t)MR_ * GP_];      // x@W + bias, row = b*T+t
__device__ float    g_rpack[(size_t)NB_ * D_ * 32]; // per-block R cols, swizzled, tf32
__device__ float    g_h[2][B_ * U_];              // ping-pong hidden state
__device__ float    g_masters[B_ * 32];           // [b][0:16]=f_m cum, [16:32]=i_m revcum
__device__ unsigned g_hflag[NUB_];
__device__ unsigned g_mflag;

// ---------------- helpers ----------------------------------------------------
__device__ __forceinline__ float rna(float x) {
    unsigned r; asm("cvt.rna.tf32.f32 %0, %1;" : "=r"(r) : "f"(x));
    return __uint_as_float(r);
}
__device__ __forceinline__ unsigned fu(float x) { return __float_as_uint(x); }

__device__ __forceinline__ void mma_tf32(float c[4], const unsigned a[4],
                                         unsigned b0, unsigned b1) {
    asm volatile(
        "mma.sync.aligned.m16n8k8.row.col.f32.tf32.tf32.f32 "
        "{%0,%1,%2,%3},{%4,%5,%6,%7},{%8,%9},{%0,%1,%2,%3};"
        : "+f"(c[0]), "+f"(c[1]), "+f"(c[2]), "+f"(c[3])
        : "r"(a[0]), "r"(a[1]), "r"(a[2]), "r"(a[3]), "r"(b0), "r"(b1));
}
__device__ __forceinline__ void cp16(void* s, const void* g) {
    unsigned a = (unsigned)__cvta_generic_to_shared(s);
    asm volatile("cp.async.cg.shared.global [%0], [%1], 16;" :: "r"(a), "l"(g));
}
__device__ __forceinline__ void cpcommit() { asm volatile("cp.async.commit_group;"); }
template<int N> __device__ __forceinline__ void cpwait() {
    asm volatile("cp.async.wait_group %0;" :: "n"(N));
}

// ---------------- prepack kernels --------------------------------------------
__global__ void k_pack_w(const float* __restrict__ W, const float* __restrict__ bias) {
    size_t i = (size_t)blockIdx.x * blockDim.x + threadIdx.x;
    if (i < (size_t)D_ * GP_) {
        int g = (int)(i % GP_);
        size_t k = i / GP_;
        g_wp[i] = (g < G_) ? rna(W[k * G_ + g]) : 0.f;
    }
    if (i < GP_) g_bp[i] = ((int)i < G_) ? bias[i] : 0.f;
}

__global__ void k_pack_r(const float* __restrict__ R) {
    int i = blockIdx.x * blockDim.x + threadIdx.x;
    if (i >= NB_ * D_ * 32) return;
    int bk  = i >> 15;          // / (1024*32)
    int rem = i & 32767;
    int k   = rem >> 5;
    int col = rem & 31;
    int src;
    if (bk == NUB_) {
        src = col;                                   // master logits cols 0..31
    } else {
        int q = col >> 3, j = col & 7;               // q: 0=f,1=i,2=o,3=g
        src = 32 + q * 1024 + bk * 8 + j;
    }
    int csw = col ^ ((k & 3) << 3);                  // smem bank swizzle
    g_rpack[((size_t)bk << 15) + (k << 5) + csw] = rna(R[(size_t)k * G_ + src]);
}

__global__ void k_zero() {
    int i = blockIdx.x * blockDim.x + threadIdx.x;
    if (i < B_ * U_) g_h[0][i] = 0.f;
    if (i < NUB_)    g_hflag[i] = 0u;
    if (i == 0)      g_mflag = 0u;
}

// ---------------- precompute GEMM: g_xk = x @ Wp + bias -----------------------
// BM=128, BN=128, BK=32, 256 threads, 8 warps (4 x 2), warp tile 32x64.
__global__ __launch_bounds__(256, 2) void k_xw(const float* __restrict__ X) {
    extern __shared__ float sm[];
    float* As = sm;                 // [2][128][36]
    float* Bs = sm + 2 * 128 * 36;  // [2][32][136]

    const int tid  = threadIdx.x;
    const int warp = tid >> 5, lane = tid & 31;
    const int grp  = lane >> 2, tig = lane & 3;
    const int wM   = (warp >> 1) * 32;
    const int wN   = (warp & 1) * 64;
    const size_t row0 = (size_t)blockIdx.y * 128;
    const int    col0 = blockIdx.x * 128;

    auto loadA = [&](int it, int buf) {
        float* dst = As + buf * 128 * 36;
        #pragma unroll
        for (int r = 0; r < 4; r++) {
            int id = tid + r * 256;                  // 0..1023
            int m = id >> 3, kq = id & 7;
            cp16(dst + m * 36 + kq * 4, X + (row0 + m) * D_ + it * 32 + kq * 4);
        }
    };
    auto loadB = [&](int it, int buf) {
        float* dst = Bs + buf * 32 * 136;
        #pragma unroll
        for (int r = 0; r < 4; r++) {
            int id = tid + r * 256;
            int k = id >> 5, nq = id & 31;
            cp16(dst + k * 136 + nq * 4,
                 g_wp + (size_t)(it * 32 + k) * GP_ + col0 + nq * 4);
        }
    };

    loadA(0, 0); loadB(0, 0); cpcommit();

    float acc[2][8][4];
    #pragma unroll
    for (int a = 0; a < 2; a++)
        #pragma unroll
        for (int b = 0; b < 8; b++)
            #pragma unroll
            for (int c = 0; c < 4; c++) acc[a][b][c] = 0.f;

    for (int it = 0; it < 32; ++it) {
        if (it < 31) {
            loadA(it + 1, (it + 1) & 1);
            loadB(it + 1, (it + 1) & 1);
            cpcommit();
            cpwait<1>();
        } else {
            cpwait<0>();
        }
        __syncthreads();
        const float* A = As + (it & 1) * 128 * 36;
        const float* B = Bs + (it & 1) * 32 * 136;
        #pragma unroll
        for (int k8 = 0; k8 < 4; k8++) {
            int kb = k8 * 8;
            unsigned a[2][4];
            #pragma unroll
            for (int mt = 0; mt < 2; mt++) {
                int m = wM + mt * 16;
                a[mt][0] = fu(rna(A[(m + grp) * 36 + kb + tig]));
                a[mt][1] = fu(rna(A[(m + grp + 8) * 36 + kb + tig]));
                a[mt][2] = fu(rna(A[(m + grp) * 36 + kb + tig + 4]));
                a[mt][3] = fu(rna(A[(m + grp + 8) * 36 + kb + tig + 4]));
            }
            #pragma unroll
            for (int nt = 0; nt < 8; nt++) {
                int n = wN + nt * 8 + grp;
                unsigned b0 = fu(B[(kb + tig) * 136 + n]);
                unsigned b1 = fu(B[(kb + tig + 4) * 136 + n]);
                mma_tf32(acc[0][nt], a[0], b0, b1);
                mma_tf32(acc[1][nt], a[1], b0, b1);
            }
        }
        __syncthreads();
    }

    // epilogue: + bias, store
    #pragma unroll
    for (int mt = 0; mt < 2; mt++) {
        #pragma unroll
        for (int nt = 0; nt < 8; nt++) {
            int m = wM + mt * 16 + grp;
            int c = wN + nt * 8 + tig * 2;
            float bv0 = g_bp[col0 + c], bv1 = g_bp[col0 + c + 1];
            size_t base = (row0 + m) * GP_ + col0 + c;
            g_xk[base]     = acc[mt][nt][0] + bv0;
            g_xk[base + 1] = acc[mt][nt][1] + bv1;
            size_t base2 = base + (size_t)8 * GP_;
            g_xk[base2]     = acc[mt][nt][2] + bv0;
            g_xk[base2 + 1] = acc[mt][nt][3] + bv1;
        }
    }
}

// ---------------- persistent recurrent kernel ---------------------------------
// 129 blocks x 256 threads. Block bk<128: units u0=bk*8..+7. Block 128: master.
__global__ __launch_bounds__(256, 1) void k_rec(float* __restrict__ out) {
    extern __shared__ float sm[];
    float* Rs = sm;            // 1024 x 32, swizzled tf32      (32768 f)
    float* As = Rs + 32768;    // [2][64][68]                   (8704 f)
    float* zs = As + 8704;     // 64 x 32                       (2048 f)
    float* xs = zs + 2048;     // 64 x 32                       (2048 f)
    float* cs = xs + 2048;     // 64 x 8 cell state             (512 f)

    const int tid  = threadIdx.x;
    const int bk   = blockIdx.x;
    const int warp = tid >> 5, lane = tid & 31;
    const int grp  = lane >> 2, tig = lane & 3;
    const int wM   = (warp >> 1) * 16;
    const int wN   = (warp & 1) * 16;
    const int u0   = bk * 8;
    const int lvl  = bk >> 3;          // level of this block's 8 units
    const bool master = (bk == NUB_);

    // load R slice (one-time), zero cell state
    {
        const float* rsrc = g_rpack + ((size_t)bk << 15);
        for (int i = tid; i < 8192; i += 256) cp16(Rs + i * 4, rsrc + i * 4);
        cpcommit(); cpwait<0>();
        for (int i = tid; i < 512; i += 256) cs[i] = 0.f;
        __syncthreads();
    }

    for (int t = 0; t < T_; ++t) {
        // wait: h input for step t ready (all unit blocks finished step t-1)
        if (tid < NUB_) {
            while (((volatile unsigned*)g_hflag)[tid] < (unsigned)t) __nanosleep(32);
        }
        __syncthreads();

        const float* hin = g_h[t & 1];

        // prefetch xk tile for this step (group 1)
        if (!master) {
            #pragma unroll
            for (int r = 0; r < 2; r++) {
                int id = tid + r * 256;           // 0..511
                int b = id >> 3, sub = id & 7;
                int q = sub >> 1, half = sub & 1;
                int col = 32 + q * 1024 + u0 + half * 4;
                cp16(xs + b * 32 + q * 8 + half * 4,
                     g_xk + ((size_t)(b * T_ + t)) * GP_ + col);
            }
        } else {
            #pragma unroll
            for (int r = 0; r < 2; r++) {
                int id = tid + r * 256;
                int b = id >> 3, c = id & 7;
                cp16(xs + b * 32 + c * 4,
                     g_xk + ((size_t)(b * T_ + t)) * GP_ + c * 4);
            }
        }
        cpcommit();

        // A(0)
        #pragma unroll
        for (int r = 0; r < 4; r++) {
            int id = tid + r * 256;               // 0..1023
            int b = id >> 4, kq = id & 15;
            cp16(As + b * 68 + kq * 4, hin + b * U_ + kq * 4);
        }
        cpcommit();

        float acc[2][4] = {{0.f,0.f,0.f,0.f},{0.f,0.f,0.f,0.f}};

        for (int it = 0; it < 16; ++it) {
            if (it < 15) {
                float* dst = As + ((it + 1) & 1) * 4352;
                #pragma unroll
                for (int r = 0; r < 4; r++) {
                    int id = tid + r * 256;
                    int b = id >> 4, kq = id & 15;
                    cp16(dst + b * 68 + kq * 4, hin + b * U_ + (it + 1) * 64 + kq * 4);
                }
                cpcommit();
                cpwait<1>();
            } else {
                cpwait<0>();
            }
            __syncthreads();
            const float* A = As + (it & 1) * 4352;
            #pragma unroll
            for (int k8 = 0; k8 < 8; k8++) {
                int kb = k8 * 8;
                unsigned a[4];
                a[0] = fu(rna(A[(wM + grp) * 68 + kb + tig]));
                a[1] = fu(rna(A[(wM + grp + 8) * 68 + kb + tig]));
                a[2] = fu(rna(A[(wM + grp) * 68 + kb + tig + 4]));
                a[3] = fu(rna(A[(wM + grp + 8) * 68 + kb + tig + 4]));
                int kk = it * 64 + kb;
                #pragma unroll
                for (int nt = 0; nt < 2; nt++) {
                    int col = wN + nt * 8 + grp;
                    int csw = col ^ (tig << 3);
                    unsigned b0 = fu(Rs[(kk + tig) * 32 + csw]);
                    unsigned b1 = fu(Rs[(kk + tig + 4) * 32 + csw]);
                    mma_tf32(acc[nt], a, b0, b1);
                }
            }
            __syncthreads();
        }

        // z = mma + xk  -> zs
        #pragma unroll
        for (int nt = 0; nt < 2; nt++) {
            int c0 = wN + nt * 8 + tig * 2;
            int r0 = wM + grp;
            zs[r0 * 32 + c0]           = acc[nt][0] + xs[r0 * 32 + c0];
            zs[r0 * 32 + c0 + 1]       = acc[nt][1] + xs[r0 * 32 + c0 + 1];
            zs[(r0 + 8) * 32 + c0]     = acc[nt][2] + xs[(r0 + 8) * 32 + c0];
            zs[(r0 + 8) * 32 + c0 + 1] = acc[nt][3] + xs[(r0 + 8) * 32 + c0 + 1];
        }
        __syncthreads();

        if (master) {
            // cumulative softmax gates -> g_masters
            if (tid < 128) {
                int b = tid >> 1, half = tid & 1;
                float v[16], mx = -1e30f;
                #pragma unroll
                for (int i = 0; i < 16; i++) {
                    v[i] = zs[b * 32 + half * 16 + i];
                    mx = fmaxf(mx, v[i]);
                }
                float s = 0.f;
                #pragma unroll
                for (int i = 0; i < 16; i++) { v[i] = expf(v[i] - mx); s += v[i]; }
                float inv = 1.f / s;
                if (half == 0) {                       // f_master: l2r cumsum
                    float run = 0.f;
                    #pragma unroll
                    for (int i = 0; i < 16; i++) {
                        run += v[i] * inv;
                        __stcg(&g_masters[b * 32 + i], run);
                    }
                } else {                               // i_master: r2l cumsum
                    float run = 0.f;
                    #pragma unroll
                    for (int i = 15; i >= 0; i--) {
                        run += v[i] * inv;
                        __stcg(&g_masters[b * 32 + 16 + i], run);
                    }
                }
            }
            __threadfence();
            __syncthreads();
            if (tid == 0) *(volatile unsigned*)&g_mflag = (unsigned)(t + 1);
        } else {
            // wait masters for this step
            while (*(volatile unsigned*)&g_mflag < (unsigned)(t + 1)) __nanosleep(32);
            __threadfence();
            float* hout = g_h[(t + 1) & 1];
            #pragma unroll
            for (int r = 0; r < 2; r++) {
                int idx = tid + r * 256;          // 0..511
                int b = idx >> 3, j = idx & 7;
                float fm = __ldcg(&g_masters[b * 32 + lvl]);
                float im = __ldcg(&g_masters[b * 32 + 16 + lvl]);
                float fz = zs[b * 32 + j];
                float iz = zs[b * 32 + 8 + j];
                float oz = zs[b * 32 + 16 + j];
                float gz = zs[b * 32 + 24 + j];
                float f = 1.f / (1.f + expf(-fz));
                float i = 1.f / (1.f + expf(-iz));
                float o = 1.f / (1.f + expf(-oz));
                float g = tanhf(gz);
                float cp = cs[b * 8 + j];
                float w = fm * im;
                float c = w * (f * cp + i * g) + (fm - w) * cp + (im - w) * g;
                cs[b * 8 + j] = c;
                float h = o * tanhf(c);
                __stcg(&hout[b * U_ + u0 + j], h);
                out[((size_t)b * T_ + t) * U_ + u0 + j] = h;
            }
            __threadfence();
            __syncthreads();
            if (tid == 0) ((volatile unsigned*)g_hflag)[bk] = (unsigned)(t + 1);
        }
    }
}

// ---------------- entry -------------------------------------------------------
extern "C" void kernel_launch(void* const* d_in, const int* in_sizes, int n_in,
                              void* d_out, int out_size) {
    const float* x    = (const float*)d_in[0];
    const float* W    = (const float*)d_in[1];
    const float* R    = (const float*)d_in[2];
    const float* bias = (const float*)d_in[3];
    float* out = (float*)d_out;

    cudaFuncSetAttribute(k_xw,  cudaFuncAttributeMaxDynamicSharedMemorySize, 71680);
    cudaFuncSetAttribute(k_rec, cudaFuncAttributeMaxDynamicSharedMemorySize, 184320);

    k_pack_w<<<(int)(((size_t)D_ * GP_ + 255) / 256), 256>>>(W, bias);
    k_pack_r<<<(NB_ * D_ * 32 + 255) / 256, 256>>>(R);
    k_zero<<<(B_ * U_ + 255) / 256, 256>>>();
    k_xw<<<dim3(GP_ / 128, MR_ / 128), 256, 71680>>>(x);
    k_rec<<<NB_, 256, 184320>>>(out);
}

// round 3
// speedup vs baseline: 1.0134x; 1.0134x over previous
#include <cuda_runtime.h>
#include <cstdint>
#include <cstddef>

#define B_     64
#define T_     512
#define D_     1024
#define U_     1024
#define L_     16
#define G_     4128
#define GP_    4224
#define NUB_   128          // unit blocks
#define NB_    129          // + 1 master block
#define MR_    32768        // B_*T_

// ---------------- static device scratch (no allocation APIs) ----------------
__device__ float    g_wp[(size_t)D_ * GP_];        // padded, tf32-rounded W
__device__ float    g_bp[GP_];                     // padded bias
__device__ float    g_xr[(size_t)MR_ * D_];        // tf32-rounded x
__device__ float    g_xk[(size_t)MR_ * GP_];       // x@W + bias, row = b*T+t
__device__ float    g_rpack[(size_t)NB_ * 8192 * 4]; // per-block R, fragment quads
__device__ float    g_hq[2][65536];                // h in fragment-quad layout, ping-pong
__device__ float    g_masters[B_ * 32];            // [b][0:16]=f_m cum, [16:32]=i_m revcum
__device__ unsigned g_ctr;                          // 129 arrivals per step
__device__ unsigned g_mflag;

// ---------------- helpers ----------------------------------------------------
__device__ __forceinline__ float rna(float x) {
    unsigned r; asm("cvt.rna.tf32.f32 %0, %1;" : "=r"(r) : "f"(x));
    return __uint_as_float(r);
}
__device__ __forceinline__ unsigned fu(float x) { return __float_as_uint(x); }

__device__ __forceinline__ void mma_tf32(float c[4], const unsigned a[4],
                                         unsigned b0, unsigned b1) {
    asm volatile(
        "mma.sync.aligned.m16n8k8.row.col.f32.tf32.tf32.f32 "
        "{%0,%1,%2,%3},{%4,%5,%6,%7},{%8,%9},{%0,%1,%2,%3};"
        : "+f"(c[0]), "+f"(c[1]), "+f"(c[2]), "+f"(c[3])
        : "r"(a[0]), "r"(a[1]), "r"(a[2]), "r"(a[3]), "r"(b0), "r"(b1));
}
__device__ __forceinline__ void cp16(void* s, const void* g) {
    unsigned a = (unsigned)__cvta_generic_to_shared(s);
    asm volatile("cp.async.cg.shared.global [%0], [%1], 16;" :: "r"(a), "l"(g));
}
__device__ __forceinline__ void cpcommit() { asm volatile("cp.async.commit_group;"); }
template<int N> __device__ __forceinline__ void cpwait() {
    asm volatile("cp.async.wait_group %0;" :: "n"(N));
}

// ---------------- prepack kernels --------------------------------------------
__global__ void k_round_x(const float* __restrict__ x) {
    size_t i = (size_t)blockIdx.x * blockDim.x + threadIdx.x;
    if (i < (size_t)MR_ * D_) g_xr[i] = rna(x[i]);
}

__global__ void k_pack_w(const float* __restrict__ W, const float* __restrict__ bias) {
    size_t i = (size_t)blockIdx.x * blockDim.x + threadIdx.x;
    if (i < (size_t)D_ * GP_) {
        int g = (int)(i % GP_);
        size_t k = i / GP_;
        g_wp[i] = (g < G_) ? rna(W[k * G_ + g]) : 0.f;
    }
    if (i < GP_) g_bp[i] = ((int)i < G_) ? bias[i] : 0.f;
}

// R packed as B-fragment quads: for block bk, quad(k16, col, tig) =
// { R[k16*16+tig][sc], R[k16*16+tig+4][sc], R[k16*16+tig+8][sc], R[k16*16+tig+12][sc] }
// quad index within block: k16*128 + col*4 + tig   (k16: 0..63, col: 0..31, tig: 0..3)
__global__ void k_pack_r(const float* __restrict__ R) {
    int i = blockIdx.x * blockDim.x + threadIdx.x;       // quad id
    if (i >= NB_ * 8192) return;
    int bk  = i >> 13;
    int rq  = i & 8191;
    int k16 = rq >> 7;
    int col = (rq >> 2) & 31;
    int tig = rq & 3;
    int sc;
    if (bk == NUB_) sc = col;                             // master logit cols
    else            sc = 32 + (col >> 3) * 1024 + bk * 8 + (col & 7);
    float4 q;
    q.x = rna(R[(size_t)(k16 * 16 + tig)      * G_ + sc]);
    q.y = rna(R[(size_t)(k16 * 16 + tig + 4)  * G_ + sc]);
    q.z = rna(R[(size_t)(k16 * 16 + tig + 8)  * G_ + sc]);
    q.w = rna(R[(size_t)(k16 * 16 + tig + 12) * G_ + sc]);
    reinterpret_cast<float4*>(g_rpack)[(size_t)bk * 8192 + rq] = q;
}

__global__ void k_zero() {
    int i = blockIdx.x * blockDim.x + threadIdx.x;
    if (i < 65536) g_hq[0][i] = 0.f;
    if (i == 0) { g_ctr = 0u; g_mflag = 0u; }
}

// ---------------- precompute GEMM: g_xk = x @ Wp + bias -----------------------
__global__ __launch_bounds__(256, 2) void k_xw() {
    extern __shared__ float sm[];
    float* As = sm;                 // [2][128][36]
    float* Bs = sm + 2 * 128 * 36;  // [2][32][136]

    const int tid  = threadIdx.x;
    const int warp = tid >> 5, lane = tid & 31;
    const int grp  = lane >> 2, tig = lane & 3;
    const int wM   = (warp >> 1) * 32;
    const int wN   = (warp & 1) * 64;
    const size_t row0 = (size_t)blockIdx.y * 128;
    const int    col0 = blockIdx.x * 128;

    auto loadA = [&](int it, int buf) {
        float* dst = As + buf * 128 * 36;
        #pragma unroll
        for (int r = 0; r < 4; r++) {
            int id = tid + r * 256;
            int m = id >> 3, kq = id & 7;
            cp16(dst + m * 36 + kq * 4, g_xr + (row0 + m) * D_ + it * 32 + kq * 4);
        }
    };
    auto loadB = [&](int it, int buf) {
        float* dst = Bs + buf * 32 * 136;
        #pragma unroll
        for (int r = 0; r < 4; r++) {
            int id = tid + r * 256;
            int k = id >> 5, nq = id & 31;
            cp16(dst + k * 136 + nq * 4,
                 g_wp + (size_t)(it * 32 + k) * GP_ + col0 + nq * 4);
        }
    };

    loadA(0, 0); loadB(0, 0); cpcommit();

    float acc[2][8][4];
    #pragma unroll
    for (int a = 0; a < 2; a++)
        #pragma unroll
        for (int b = 0; b < 8; b++)
            #pragma unroll
            for (int c = 0; c < 4; c++) acc[a][b][c] = 0.f;

    for (int it = 0; it < 32; ++it) {
        if (it < 31) {
            loadA(it + 1, (it + 1) & 1);
            loadB(it + 1, (it + 1) & 1);
            cpcommit();
            cpwait<1>();
        } else {
            cpwait<0>();
        }
        __syncthreads();
        const float* A = As + (it & 1) * 128 * 36;
        const float* B = Bs + (it & 1) * 32 * 136;
        #pragma unroll
        for (int k8 = 0; k8 < 4; k8++) {
            int kb = k8 * 8;
            unsigned a[2][4];
            #pragma unroll
            for (int mt = 0; mt < 2; mt++) {
                int m = wM + mt * 16;
                a[mt][0] = fu(A[(m + grp) * 36 + kb + tig]);
                a[mt][1] = fu(A[(m + grp + 8) * 36 + kb + tig]);
                a[mt][2] = fu(A[(m + grp) * 36 + kb + tig + 4]);
                a[mt][3] = fu(A[(m + grp + 8) * 36 + kb + tig + 4]);
            }
            #pragma unroll
            for (int nt = 0; nt < 8; nt++) {
                int n = wN + nt * 8 + grp;
                unsigned b0 = fu(B[(kb + tig) * 136 + n]);
                unsigned b1 = fu(B[(kb + tig + 4) * 136 + n]);
                mma_tf32(acc[0][nt], a[0], b0, b1);
                mma_tf32(acc[1][nt], a[1], b0, b1);
            }
        }
        __syncthreads();
    }

    #pragma unroll
    for (int mt = 0; mt < 2; mt++) {
        #pragma unroll
        for (int nt = 0; nt < 8; nt++) {
            int m = wM + mt * 16 + grp;
            int c = wN + nt * 8 + tig * 2;
            float bv0 = g_bp[col0 + c], bv1 = g_bp[col0 + c + 1];
            size_t base = (row0 + m) * GP_ + col0 + c;
            g_xk[base]     = acc[mt][nt][0] + bv0;
            g_xk[base + 1] = acc[mt][nt][1] + bv1;
            size_t base2 = base + (size_t)8 * GP_;
            g_xk[base2]     = acc[mt][nt][2] + bv0;
            g_xk[base2 + 1] = acc[mt][nt][3] + bv1;
        }
    }
}

// ---------------- persistent recurrent kernel ---------------------------------
// h quad layout: qid = ku*128 + bgrp*32 + tig*8 + brow,
//   quad = { h(b,u), h(b+8,u), h(b,u+4), h(b+8,u+4) },  b = bgrp*16+brow, u = ku*8+tig
__global__ __launch_bounds__(256, 1) void k_rec(float* __restrict__ out) {
    extern __shared__ float sm[];
    float* Rs = sm;            // 8192 quads = 32768 floats (fragment order)
    float* As = Rs + 32768;    // [2][2048 quads] = 16384 floats
    float* zs = As + 16384;    // 64 x 32
    float* xs = zs + 2048;     // 64 x 32
    float* cs = xs + 2048;     // 64 x 8 cell state

    float4* Rs4 = reinterpret_cast<float4*>(Rs);
    float4* As4 = reinterpret_cast<float4*>(As);

    const int tid  = threadIdx.x;
    const int bk   = blockIdx.x;
    const int warp = tid >> 5, lane = tid & 31;
    const int grp  = lane >> 2, tig = lane & 3;
    const int bgrp = warp >> 1;                    // A row-group (wM = bgrp*16)
    const int wN   = (warp & 1) * 16;
    const int u0   = bk * 8;
    const int lvl  = bk >> 3;
    const bool master = (bk == NUB_);

    // one-time: R slice -> smem, zero cell state
    {
        const float4* rsrc = reinterpret_cast<const float4*>(g_rpack) + (size_t)bk * 8192;
        for (int i = tid; i < 8192; i += 256) cp16(Rs4 + i, rsrc + i);
        cpcommit(); cpwait<0>();
        for (int i = tid; i < 512; i += 256) cs[i] = 0.f;
        __syncthreads();
    }

    for (int t = 0; t < T_; ++t) {
        // gate: all 129 blocks finished step t-1 (h_t written, buffers reusable)
        if (tid == 0) {
            unsigned target = 129u * (unsigned)t;
            while (*(volatile unsigned*)&g_ctr < target) __nanosleep(32);
        }
        __syncthreads();

        const float4* hin4 = reinterpret_cast<const float4*>(g_hq[t & 1]);

        // prefetch xk tile for this step
        if (!master) {
            #pragma unroll
            for (int r = 0; r < 2; r++) {
                int id = tid + r * 256;
                int b = id >> 3, sub = id & 7;
                int q = sub >> 1, half = sub & 1;
                int col = 32 + q * 1024 + u0 + half * 4;
                cp16(xs + b * 32 + q * 8 + half * 4,
                     g_xk + ((size_t)(b * T_ + t)) * GP_ + col);
            }
        } else {
            #pragma unroll
            for (int r = 0; r < 2; r++) {
                int id = tid + r * 256;
                int b = id >> 3, c = id & 7;
                cp16(xs + b * 32 + c * 4,
                     g_xk + ((size_t)(b * T_ + t)) * GP_ + c * 4);
            }
        }
        cpcommit();

        // A chunk 0 (2048 quads = 32KB contiguous)
        #pragma unroll
        for (int r = 0; r < 8; r++) {
            int q = tid + r * 256;
            cp16(As4 + q, hin4 + q);
        }
        cpcommit();

        float acc[2][4] = {{0.f,0.f,0.f,0.f},{0.f,0.f,0.f,0.f}};

        for (int it = 0; it < 8; ++it) {
            if (it < 7) {
                float4* dst = As4 + ((it + 1) & 1) * 2048;
                const float4* src = hin4 + (it + 1) * 2048;
                #pragma unroll
                for (int r = 0; r < 8; r++) {
                    int q = tid + r * 256;
                    cp16(dst + q, src + q);
                }
                cpcommit();
                cpwait<1>();
            } else {
                cpwait<0>();
            }
            __syncthreads();
            const float4* A = As4 + (it & 1) * 2048;
            #pragma unroll
            for (int k16 = 0; k16 < 8; k16++) {
                int kug = it * 16 + k16 * 2;           // global ku of first k8
                // A fragments: one v4 per k8
                float4 aq0 = A[(k16 * 2)     * 128 + bgrp * 32 + tig * 8 + grp];
                float4 aq1 = A[(k16 * 2 + 1) * 128 + bgrp * 32 + tig * 8 + grp];
                unsigned a0[4] = { fu(aq0.x), fu(aq0.y), fu(aq0.z), fu(aq0.w) };
                unsigned a1[4] = { fu(aq1.x), fu(aq1.y), fu(aq1.z), fu(aq1.w) };
                int k16g = it * 8 + k16;
                #pragma unroll
                for (int nt = 0; nt < 2; nt++) {
                    int col = wN + nt * 8 + grp;
                    float4 bq = Rs4[k16g * 128 + col * 4 + tig];
                    mma_tf32(acc[nt], a0, fu(bq.x), fu(bq.y));
                    mma_tf32(acc[nt], a1, fu(bq.z), fu(bq.w));
                }
                (void)kug;
            }
            __syncthreads();
        }

        // z = mma + xk -> zs
        {
            int wM = bgrp * 16;
            #pragma unroll
            for (int nt = 0; nt < 2; nt++) {
                int c0 = wN + nt * 8 + tig * 2;
                int r0 = wM + grp;
                zs[r0 * 32 + c0]           = acc[nt][0] + xs[r0 * 32 + c0];
                zs[r0 * 32 + c0 + 1]       = acc[nt][1] + xs[r0 * 32 + c0 + 1];
                zs[(r0 + 8) * 32 + c0]     = acc[nt][2] + xs[(r0 + 8) * 32 + c0];
                zs[(r0 + 8) * 32 + c0 + 1] = acc[nt][3] + xs[(r0 + 8) * 32 + c0 + 1];
            }
        }
        __syncthreads();

        if (master) {
            if (tid < 128) {
                int b = tid >> 1, half = tid & 1;
                float v[16], mx = -1e30f;
                #pragma unroll
                for (int i = 0; i < 16; i++) {
                    v[i] = zs[b * 32 + half * 16 + i];
                    mx = fmaxf(mx, v[i]);
                }
                float s = 0.f;
                #pragma unroll
                for (int i = 0; i < 16; i++) { v[i] = expf(v[i] - mx); s += v[i]; }
                float inv = 1.f / s;
                if (half == 0) {
                    float run = 0.f;
                    #pragma unroll
                    for (int i = 0; i < 16; i++) {
                        run += v[i] * inv;
                        __stcg(&g_masters[b * 32 + i], run);
                    }
                } else {
                    float run = 0.f;
                    #pragma unroll
                    for (int i = 15; i >= 0; i--) {
                        run += v[i] * inv;
                        __stcg(&g_masters[b * 32 + 16 + i], run);
                    }
                }
            }
            __threadfence();
            __syncthreads();
            if (tid == 0) {
                *(volatile unsigned*)&g_mflag = (unsigned)(t + 1);
                atomicAdd(&g_ctr, 1u);
            }
        } else {
            if (tid == 0) {
                while (*(volatile unsigned*)&g_mflag < (unsigned)(t + 1)) __nanosleep(32);
            }
            __syncthreads();
            float4* hout4 = reinterpret_cast<float4*>(g_hq[(t + 1) & 1]);
            if (tid < 128) {
                int bg   = tid >> 5;
                int tg   = (tid >> 3) & 3;
                int brow = tid & 7;
                int b0v  = bg * 16 + brow;
                float fm0 = __ldcg(&g_masters[b0v * 32 + lvl]);
                float im0 = __ldcg(&g_masters[b0v * 32 + 16 + lvl]);
                float fm1 = __ldcg(&g_masters[(b0v + 8) * 32 + lvl]);
                float im1 = __ldcg(&g_masters[(b0v + 8) * 32 + 16 + lvl]);
                float hv[4];
                #pragma unroll
                for (int e = 0; e < 4; e++) {
                    int b = b0v + ((e & 1) ? 8 : 0);
                    int j = tg + ((e >> 1) ? 4 : 0);
                    float fm = (e & 1) ? fm1 : fm0;
                    float im = (e & 1) ? im1 : im0;
                    float fz = zs[b * 32 + j];
                    float iz = zs[b * 32 + 8 + j];
                    float oz = zs[b * 32 + 16 + j];
                    float gz = zs[b * 32 + 24 + j];
                    float f = 1.f / (1.f + expf(-fz));
                    float i = 1.f / (1.f + expf(-iz));
                    float o = 1.f / (1.f + expf(-oz));
                    float g = tanhf(gz);
                    float cp = cs[b * 8 + j];
                    float w = fm * im;
                    float c = w * (f * cp + i * g) + (fm - w) * cp + (im - w) * g;
                    cs[b * 8 + j] = c;
                    float h = o * tanhf(c);
                    hv[e] = h;
                    out[((size_t)b * T_ + t) * U_ + u0 + j] = h;
                }
                float4 q;
                q.x = rna(hv[0]); q.y = rna(hv[1]); q.z = rna(hv[2]); q.w = rna(hv[3]);
                hout4[bk * 128 + bg * 32 + tg * 8 + brow] = q;
            }
            __threadfence();
            __syncthreads();
            if (tid == 0) atomicAdd(&g_ctr, 1u);
        }
    }
}

// ---------------- entry -------------------------------------------------------
extern "C" void kernel_launch(void* const* d_in, const int* in_sizes, int n_in,
                              void* d_out, int out_size) {
    const float* x    = (const float*)d_in[0];
    const float* W    = (const float*)d_in[1];
    const float* R    = (const float*)d_in[2];
    const float* bias = (const float*)d_in[3];
    float* out = (float*)d_out;

    cudaFuncSetAttribute(k_xw,  cudaFuncAttributeMaxDynamicSharedMemorySize, 71680);
    cudaFuncSetAttribute(k_rec, cudaFuncAttributeMaxDynamicSharedMemorySize, 215040);

    k_round_x<<<(int)(((size_t)MR_ * D_ + 255) / 256), 256>>>(x);
    k_pack_w<<<(int)(((size_t)D_ * GP_ + 255) / 256), 256>>>(W, bias);
    k_pack_r<<<(NB_ * 8192 + 255) / 256, 256>>>(R);
    k_zero<<<(65536 + 255) / 256, 256>>>();
    k_xw<<<dim3(GP_ / 128, MR_ / 128), 256, 71680>>>();
    k_rec<<<NB_, 256, 215040>>>(out);
}

// round 5
// speedup vs baseline: 2.2116x; 2.1823x over previous
#include <cuda_runtime.h>
#include <cuda_fp16.h>
#include <cstdint>
#include <cstddef>

#define B_     64
#define T_     512
#define D_     1024
#define U_     1024
#define L_     16
#define G_     4128
#define GP_    4224
#define NT_    33           // GP_/128 column tiles
#define NTM_   256          // MR_/128 row tiles
#define NUB_   128          // unit blocks
#define NB_    129          // + 1 master block
#define MR_    32768        // B_*T_

// ---------------- static device scratch (no allocation APIs) ----------------
__device__ __align__(256) uint4 g_xq[(size_t)NTM_ * 16384]; // x fp16 A-frag quads
__device__ __align__(256) uint4 g_wq[(size_t)NT_ * 16384];  // W fp16 B-frag quads
__device__ __align__(256) uint4 g_rq[(size_t)NB_ * 4096];   // R fp16 B-frag quads per block
__device__ __align__(256) uint4 g_hq[2][8192];              // h fp16 A-frag quads, ping-pong
__device__ __align__(256) float g_bp[GP_];                  // padded bias
__device__ __align__(256) float g_xk[(size_t)MR_ * GP_];    // x@W + bias (f32)
__device__ __align__(256) float g_masters[B_ * 32];
__device__ unsigned g_ctr;
__device__ unsigned g_mflag;

// ---------------- helpers ----------------------------------------------------
__device__ __forceinline__ unsigned pack2(float lo, float hi) {
    __half2 h = __floats2half2_rn(lo, hi);
    return *reinterpret_cast<unsigned*>(&h);
}

__device__ __forceinline__ void mma_f16(float c[4], unsigned a0, unsigned a1,
                                        unsigned a2, unsigned a3,
                                        unsigned b0, unsigned b1) {
    asm volatile(
        "mma.sync.aligned.m16n8k16.row.col.f32.f16.f16.f32 "
        "{%0,%1,%2,%3},{%4,%5,%6,%7},{%8,%9},{%0,%1,%2,%3};"
        : "+f"(c[0]), "+f"(c[1]), "+f"(c[2]), "+f"(c[3])
        : "r"(a0), "r"(a1), "r"(a2), "r"(a3), "r"(b0), "r"(b1));
}
__device__ __forceinline__ void cp16(void* s, const void* g) {
    unsigned a = (unsigned)__cvta_generic_to_shared(s);
    asm volatile("cp.async.cg.shared.global [%0], [%1], 16;" :: "r"(a), "l"(g));
}
__device__ __forceinline__ void cpcommit() { asm volatile("cp.async.commit_group;"); }
template<int N> __device__ __forceinline__ void cpwait() {
    asm volatile("cp.async.wait_group %0;" :: "n"(N));
}

// ---------------- prepack kernels --------------------------------------------
// A-frag quads for x: qid = tile*16384 + ku*256 + mgrp*32 + lane
// quad = {a0,a1,a2,a3} of m16n8k16 for rows (tile*128+mgrp*16+grp, +8), k=ku*16+2tig..
__global__ void k_pack_xq(const float* __restrict__ x) {
    size_t qid = (size_t)blockIdx.x * blockDim.x + threadIdx.x;
    if (qid >= (size_t)NTM_ * 16384) return;
    int tile = (int)(qid >> 14);
    int rem  = (int)(qid & 16383);
    int ku   = rem >> 8;
    int mgrp = (rem >> 5) & 7;
    int lane = rem & 31;
    int grp = lane >> 2, tig = lane & 3;
    int r0 = tile * 128 + mgrp * 16 + grp;
    int k0 = ku * 16 + 2 * tig;
    const float* x0 = x + (size_t)r0 * D_;
    const float* x1 = x0 + (size_t)8 * D_;
    uint4 q;
    q.x = pack2(x0[k0],     x0[k0 + 1]);
    q.y = pack2(x1[k0],     x1[k0 + 1]);
    q.z = pack2(x0[k0 + 8], x0[k0 + 9]);
    q.w = pack2(x1[k0 + 8], x1[k0 + 9]);
    g_xq[qid] = q;
}

// B-frag quads for W: qid = nt*16384 + ku2*512 + ng*32 + lane
// quad = {b0(kuE), b1(kuE), b0(kuO), b1(kuO)} for col = nt*128+ng*8+grp
__global__ void k_pack_wq(const float* __restrict__ W, const float* __restrict__ bias) {
    size_t qid = (size_t)blockIdx.x * blockDim.x + threadIdx.x;
    if (qid < (size_t)NT_ * 16384) {
        int nt  = (int)(qid >> 14);
        int rem = (int)(qid & 16383);
        int ku2 = rem >> 9;
        int ng  = (rem >> 5) & 15;
        int lane = rem & 31;
        int grp = lane >> 2, tig = lane & 3;
        int col = nt * 128 + ng * 8 + grp;
        int kb = ku2 * 32 + 2 * tig;
        uint4 q;
        if (col < G_) {
            const float* Wc = W + col;
            q.x = pack2(Wc[(size_t)(kb)      * G_], Wc[(size_t)(kb + 1)  * G_]);
            q.y = pack2(Wc[(size_t)(kb + 8)  * G_], Wc[(size_t)(kb + 9)  * G_]);
            q.z = pack2(Wc[(size_t)(kb + 16) * G_], Wc[(size_t)(kb + 17) * G_]);
            q.w = pack2(Wc[(size_t)(kb + 24) * G_], Wc[(size_t)(kb + 25) * G_]);
        } else {
            q = make_uint4(0u, 0u, 0u, 0u);
        }
        g_wq[qid] = q;
    }
    if (qid < GP_) g_bp[qid] = ((int)qid < G_) ? bias[qid] : 0.f;
}

// B-frag quads for R (per recurrent block): qid = bk*4096 + ku2*128 + col*4 + tig
__global__ void k_pack_rq(const float* __restrict__ R) {
    int qid = blockIdx.x * blockDim.x + threadIdx.x;
    if (qid >= NB_ * 4096) return;
    int bk  = qid >> 12;
    int rem = qid & 4095;
    int ku2 = rem >> 7;
    int col = (rem >> 2) & 31;
    int tig = rem & 3;
    int sc;
    if (bk == NUB_) sc = col;
    else            sc = 32 + (col >> 3) * 1024 + bk * 8 + (col & 7);
    int kb = ku2 * 32 + 2 * tig;
    const float* Rc = R + sc;
    uint4 q;
    q.x = pack2(Rc[(size_t)(kb)      * G_], Rc[(size_t)(kb + 1)  * G_]);
    q.y = pack2(Rc[(size_t)(kb + 8)  * G_], Rc[(size_t)(kb + 9)  * G_]);
    q.z = pack2(Rc[(size_t)(kb + 16) * G_], Rc[(size_t)(kb + 17) * G_]);
    q.w = pack2(Rc[(size_t)(kb + 24) * G_], Rc[(size_t)(kb + 25) * G_]);
    g_rq[qid] = q;
}

__global__ void k_zero() {
    int i = blockIdx.x * blockDim.x + threadIdx.x;
    if (i < 8192) g_hq[0][i] = make_uint4(0u, 0u, 0u, 0u);
    if (i == 0) { g_ctr = 0u; g_mflag = 0u; }
}

// ---------------- precompute GEMM: g_xk = x @ W + bias (fp16 mma) -------------
// Tile 128x128, BK=64 (4 k16), 256 threads / 8 warps (4x2), warp tile 32x64.
__global__ __launch_bounds__(256, 2) void k_xw() {
    extern __shared__ uint4 sm4[];
    uint4* As4 = sm4;          // [2][1024]
    uint4* Bs4 = sm4 + 2048;   // [2][1024]

    const int tid  = threadIdx.x;
    const int warp = tid >> 5, lane = tid & 31;
    const int grp  = lane >> 2, tig = lane & 3;
    const int wMg  = (warp >> 1) * 2;         // m16-group base (rows wMg*16)
    const int wNg  = (warp & 1) * 8;          // n8-group base (cols wNg*8)
    const int nt_blk = blockIdx.x;
    const size_t row0 = (size_t)blockIdx.y * 128;

    const uint4* Asrc = g_xq + (size_t)blockIdx.y * 16384;
    const uint4* Bsrc = g_wq + (size_t)nt_blk * 16384;

    auto load_chunk = [&](int kc, int buf) {
        const uint4* as = Asrc + kc * 1024;
        const uint4* bs = Bsrc + kc * 1024;
        uint4* ad = As4 + buf * 1024;
        uint4* bd = Bs4 + buf * 1024;
        #pragma unroll
        for (int r = 0; r < 4; r++) cp16(ad + tid + r * 256, as + tid + r * 256);
        #pragma unroll
        for (int r = 0; r < 4; r++) cp16(bd + tid + r * 256, bs + tid + r * 256);
        cpcommit();
    };

    load_chunk(0, 0);

    float acc[2][8][4];
    #pragma unroll
    for (int a = 0; a < 2; a++)
        #pragma unroll
        for (int b = 0; b < 8; b++)
            #pragma unroll
            for (int c = 0; c < 4; c++) acc[a][b][c] = 0.f;

    for (int kc = 0; kc < 16; ++kc) {
        if (kc < 15) { load_chunk(kc + 1, (kc + 1) & 1); cpwait<1>(); }
        else         { cpwait<0>(); }
        __syncthreads();
        const uint4* A = As4 + (kc & 1) * 1024;
        const uint4* B = Bs4 + (kc & 1) * 1024;
        #pragma unroll
        for (int ku2l = 0; ku2l < 2; ku2l++) {
            #pragma unroll
            for (int par = 0; par < 2; par++) {
                int kul = ku2l * 2 + par;
                uint4 a0q = A[kul * 256 + wMg * 32 + lane];
                uint4 a1q = A[kul * 256 + (wMg + 1) * 32 + lane];
                #pragma unroll
                for (int nt = 0; nt < 8; nt++) {
                    uint4 bq = B[ku2l * 512 + (wNg + nt) * 32 + lane];
                    unsigned b0 = par ? bq.z : bq.x;
                    unsigned b1 = par ? bq.w : bq.y;
                    mma_f16(acc[0][nt], a0q.x, a0q.y, a0q.z, a0q.w, b0, b1);
                    mma_f16(acc[1][nt], a1q.x, a1q.y, a1q.z, a1q.w, b0, b1);
                }
            }
        }
        __syncthreads();
    }

    // epilogue: + bias, store f32
    const int colbase = nt_blk * 128 + (warp & 1) * 64;
    const int wM = (warp >> 1) * 32;
    #pragma unroll
    for (int nt = 0; nt < 8; nt++) {
        int gc = colbase + nt * 8 + 2 * tig;
        float bv0 = g_bp[gc], bv1 = g_bp[gc + 1];
        #pragma unroll
        for (int mt = 0; mt < 2; mt++) {
            size_t gr = row0 + wM + mt * 16 + grp;
            size_t base = gr * GP_ + gc;
            g_xk[base]     = acc[mt][nt][0] + bv0;
            g_xk[base + 1] = acc[mt][nt][1] + bv1;
            size_t base2 = base + (size_t)8 * GP_;
            g_xk[base2]     = acc[mt][nt][2] + bv0;
            g_xk[base2 + 1] = acc[mt][nt][3] + bv1;
        }
    }
}

// ---------------- persistent recurrent kernel (fp16 mma) ----------------------
// smem: Rs4 4096 uint4 (64KB), As4 8192 uint4 (128KB, full h), zs/xs/cs f32.
__global__ __launch_bounds__(256, 1) void k_rec(float* __restrict__ out) {
    extern __shared__ uint4 sm4[];
    uint4* Rs4 = sm4;            // 4096
    uint4* As4 = sm4 + 4096;     // 8192
    float* zs  = (float*)(sm4 + 4096 + 8192);  // 64 x 32
    float* xs  = zs + 2048;                    // 64 x 32
    float* cs  = xs + 2048;                    // 64 x 8

    const int tid  = threadIdx.x;
    const int bk   = blockIdx.x;
    const int warp = tid >> 5, lane = tid & 31;
    const int grp  = lane >> 2, tig = lane & 3;
    const int bgrp = warp >> 1;                // A row group (rows bgrp*16..)
    const int wN   = (warp & 1) * 16;
    const int u0   = bk * 8;
    const int lvl  = bk >> 3;
    const bool master = (bk == NUB_);

    // one-time: R slice -> smem, zero cell state
    {
        const uint4* rsrc = g_rq + (size_t)bk * 4096;
        #pragma unroll
        for (int r = 0; r < 16; r++) cp16(Rs4 + tid + r * 256, rsrc + tid + r * 256);
        cpcommit(); cpwait<0>();
        for (int i = tid; i < 512; i += 256) cs[i] = 0.f;
        __syncthreads();
    }

    for (int t = 0; t < T_; ++t) {
        if (tid == 0) {
            unsigned target = 129u * (unsigned)t;
            while (*(volatile unsigned*)&g_ctr < target) __nanosleep(32);
        }
        __syncthreads();

        const uint4* hin4 = g_hq[t & 1];

        // group 1: xk tile prefetch
        if (!master) {
            #pragma unroll
            for (int r = 0; r < 2; r++) {
                int id = tid + r * 256;
                int b = id >> 3, sub = id & 7;
                int q = sub >> 1, half = sub & 1;
                int col = 32 + q * 1024 + u0 + half * 4;
                cp16(xs + b * 32 + q * 8 + half * 4,
                     g_xk + ((size_t)(b * T_ + t)) * GP_ + col);
            }
        } else {
            #pragma unroll
            for (int r = 0; r < 2; r++) {
                int id = tid + r * 256;
                int b = id >> 3, c = id & 7;
                cp16(xs + b * 32 + c * 4,
                     g_xk + ((size_t)(b * T_ + t)) * GP_ + c * 4);
            }
        }
        cpcommit();

        // group 2: h first half (ku 0..31), group 3: h second half
        #pragma unroll
        for (int r = 0; r < 16; r++) cp16(As4 + tid + r * 256, hin4 + tid + r * 256);
        cpcommit();
        #pragma unroll
        for (int r = 16; r < 32; r++) cp16(As4 + tid + r * 256, hin4 + tid + r * 256);
        cpcommit();

        float acc[2][4] = {{0.f,0.f,0.f,0.f},{0.f,0.f,0.f,0.f}};

        #pragma unroll 1
        for (int half = 0; half < 2; half++) {
            if (half == 0) cpwait<1>(); else cpwait<0>();
            __syncthreads();
            const int ku2_0 = half * 16;
            #pragma unroll
            for (int k = 0; k < 16; k++) {
                int ku2 = ku2_0 + k;
                uint4 aE = As4[(2 * ku2)     * 128 + bgrp * 32 + lane];
                uint4 aO = As4[(2 * ku2 + 1) * 128 + bgrp * 32 + lane];
                #pragma unroll
                for (int nt = 0; nt < 2; nt++) {
                    int col = wN + nt * 8 + grp;
                    uint4 bq = Rs4[ku2 * 128 + col * 4 + tig];
                    mma_f16(acc[nt], aE.x, aE.y, aE.z, aE.w, bq.x, bq.y);
                    mma_f16(acc[nt], aO.x, aO.y, aO.z, aO.w, bq.z, bq.w);
                }
            }
        }

        // z = mma + xk -> zs
        {
            int wM = bgrp * 16;
            #pragma unroll
            for (int nt = 0; nt < 2; nt++) {
                int c0 = wN + nt * 8 + tig * 2;
                int r0 = wM + grp;
                zs[r0 * 32 + c0]           = acc[nt][0] + xs[r0 * 32 + c0];
                zs[r0 * 32 + c0 + 1]       = acc[nt][1] + xs[r0 * 32 + c0 + 1];
                zs[(r0 + 8) * 32 + c0]     = acc[nt][2] + xs[(r0 + 8) * 32 + c0];
                zs[(r0 + 8) * 32 + c0 + 1] = acc[nt][3] + xs[(r0 + 8) * 32 + c0 + 1];
            }
        }
        __syncthreads();

        if (master) {
            if (tid < 128) {
                int b = tid >> 1, half = tid & 1;
                float v[16], mx = -1e30f;
                #pragma unroll
                for (int i = 0; i < 16; i++) {
                    v[i] = zs[b * 32 + half * 16 + i];
                    mx = fmaxf(mx, v[i]);
                }
                float s = 0.f;
                #pragma unroll
                for (int i = 0; i < 16; i++) { v[i] = expf(v[i] - mx); s += v[i]; }
                float inv = 1.f / s;
                if (half == 0) {
                    float run = 0.f;
                    #pragma unroll
                    for (int i = 0; i < 16; i++) {
                        run += v[i] * inv;
                        __stcg(&g_masters[b * 32 + i], run);
                    }
                } else {
                    float run = 0.f;
                    #pragma unroll
                    for (int i = 15; i >= 0; i--) {
                        run += v[i] * inv;
                        __stcg(&g_masters[b * 32 + 16 + i], run);
                    }
                }
            }
            __threadfence();
            __syncthreads();
            if (tid == 0) {
                *(volatile unsigned*)&g_mflag = (unsigned)(t + 1);
                atomicAdd(&g_ctr, 1u);
            }
        } else {
            if (tid == 0) {
                while (*(volatile unsigned*)&g_mflag < (unsigned)(t + 1)) __nanosleep(32);
            }
            __syncthreads();
            uint4* hout4 = g_hq[(t + 1) & 1];
            if (tid < 128) {
                int bg   = tid >> 5;
                int ln   = tid & 31;
                int gp   = ln >> 2, tg = ln & 3;
                int r    = bg * 16 + gp;
                int j0   = 2 * tg;
                float fmA = __ldcg(&g_masters[r * 32 + lvl]);
                float imA = __ldcg(&g_masters[r * 32 + 16 + lvl]);
                float fmB = __ldcg(&g_masters[(r + 8) * 32 + lvl]);
                float imB = __ldcg(&g_masters[(r + 8) * 32 + 16 + lvl]);
                float hv[4];
                #pragma unroll
                for (int e = 0; e < 4; e++) {
                    int row = r + ((e >> 1) ? 8 : 0);
                    int j = j0 + (e & 1);
                    float fm = (e >> 1) ? fmB : fmA;
                    float im = (e >> 1) ? imB : imA;
                    float fz = zs[row * 32 + j];
                    float iz = zs[row * 32 + 8 + j];
                    float oz = zs[row * 32 + 16 + j];
                    float gz = zs[row * 32 + 24 + j];
                    float f = 1.f / (1.f + expf(-fz));
                    float i = 1.f / (1.f + expf(-iz));
                    float o = 1.f / (1.f + expf(-oz));
                    float g = tanhf(gz);
                    float cp = cs[row * 8 + j];
                    float w = fm * im;
                    float c = w * (f * cp + i * g) + (fm - w) * cp + (im - w) * g;
                    cs[row * 8 + j] = c;
                    float h = o * tanhf(c);
                    hv[e] = h;
                    out[((size_t)row * T_ + t) * U_ + u0 + j] = h;
                }
                unsigned w0 = pack2(hv[0], hv[1]);   // row r,   units j0, j0+1
                unsigned w1 = pack2(hv[2], hv[3]);   // row r+8, units j0, j0+1
                char* dst = (char*)(hout4 + (bk >> 1) * 128 + bg * 32 + ln) + (bk & 1) * 8;
                asm volatile("st.global.cg.v2.u32 [%0], {%1,%2};"
                             :: "l"(dst), "r"(w0), "r"(w1) : "memory");
            }
            __threadfence();
            __syncthreads();
            if (tid == 0) atomicAdd(&g_ctr, 1u);
        }
    }
}

// ---------------- entry -------------------------------------------------------
extern "C" void kernel_launch(void* const* d_in, const int* in_sizes, int n_in,
                              void* d_out, int out_size) {
    const float* x    = (const float*)d_in[0];
    const float* W    = (const float*)d_in[1];
    const float* R    = (const float*)d_in[2];
    const float* bias = (const float*)d_in[3];
    float* out = (float*)d_out;

    cudaFuncSetAttribute(k_xw,  cudaFuncAttributeMaxDynamicSharedMemorySize, 65536);
    cudaFuncSetAttribute(k_rec, cudaFuncAttributeMaxDynamicSharedMemorySize, 215040);

    k_pack_xq<<<(int)(((size_t)NTM_ * 16384 + 255) / 256), 256>>>(x);
    k_pack_wq<<<(int)(((size_t)NT_ * 16384 + 255) / 256), 256>>>(W, bias);
    k_pack_rq<<<(NB_ * 4096 + 255) / 256, 256>>>(R);
    k_zero<<<32, 256>>>();
    k_xw<<<dim3(NT_, NTM_), 256, 65536>>>();
    k_rec<<<NB_, 256, 215040>>>(out);
}

// round 6
// speedup vs baseline: 2.3931x; 1.0820x over previous
#include <cuda_runtime.h>
#include <cuda_fp16.h>
#include <cstdint>
#include <cstddef>

#define B_     64
#define T_     512
#define D_     1024
#define U_     1024
#define G_     4128
#define NUB_   128          // unit blocks
#define NB_    129          // + 1 master block

// ---------------- static device scratch (no allocation APIs) ----------------
__device__ __align__(256) uint4 g_xtq[(size_t)T_ * 8192]; // x A-frag quads, per-step (64MB)
__device__ __align__(256) uint4 g_bq[(size_t)NB_ * 8192]; // [W;R] B-frag quads per block
__device__ __align__(256) uint4 g_hq[2][8192];            // h A-frag quads, ping-pong
__device__ __align__(256) float g_masters[B_ * 32];
__device__ unsigned g_ctr;
__device__ unsigned g_mflag;

// ---------------- helpers ----------------------------------------------------
__device__ __forceinline__ unsigned pack2(float lo, float hi) {
    __half2 h = __floats2half2_rn(lo, hi);
    return *reinterpret_cast<unsigned*>(&h);
}
__device__ __forceinline__ void mma_f16(float c[4], unsigned a0, unsigned a1,
                                        unsigned a2, unsigned a3,
                                        unsigned b0, unsigned b1) {
    asm volatile(
        "mma.sync.aligned.m16n8k16.row.col.f32.f16.f16.f32 "
        "{%0,%1,%2,%3},{%4,%5,%6,%7},{%8,%9},{%0,%1,%2,%3};"
        : "+f"(c[0]), "+f"(c[1]), "+f"(c[2]), "+f"(c[3])
        : "r"(a0), "r"(a1), "r"(a2), "r"(a3), "r"(b0), "r"(b1));
}
__device__ __forceinline__ void cp16(void* s, const void* g) {
    unsigned a = (unsigned)__cvta_generic_to_shared(s);
    asm volatile("cp.async.cg.shared.global [%0], [%1], 16;" :: "r"(a), "l"(g));
}
__device__ __forceinline__ void cpcommit() { asm volatile("cp.async.commit_group;"); }
template<int N> __device__ __forceinline__ void cpwait() {
    asm volatile("cp.async.wait_group %0;" :: "n"(N));
}

// ---------------- prepack kernels --------------------------------------------
// x A-frag quads, t-major: g_xtq[t*8192 + ku*128 + mgrp*32 + lane]
// quad = {a0,a1,a2,a3} for batch rows (mgrp*16+grp, +8), k = ku*16 + 2tig (+0,1 / +8,9)
__global__ void k_pack_aq(const float* __restrict__ x) {
    size_t qid = (size_t)blockIdx.x * 256 + threadIdx.x;
    if (qid >= (size_t)T_ * 8192) return;
    int t    = (int)(qid >> 13);
    int rem  = (int)(qid & 8191);
    int ku   = rem >> 7;
    int mgrp = (rem >> 5) & 3;
    int lane = rem & 31;
    int grp = lane >> 2, tig = lane & 3;
    int b0 = mgrp * 16 + grp;
    int k0 = ku * 16 + 2 * tig;
    const float* x0 = x + ((size_t)b0 * T_ + t) * D_;
    const float* x1 = x + ((size_t)(b0 + 8) * T_ + t) * D_;
    uint4 q;
    q.x = pack2(x0[k0],     x0[k0 + 1]);
    q.y = pack2(x1[k0],     x1[k0 + 1]);
    q.z = pack2(x0[k0 + 8], x0[k0 + 9]);
    q.w = pack2(x1[k0 + 8], x1[k0 + 9]);
    g_xtq[qid] = q;
}

// [W;R] B-frag quads per block: g_bq[bk*8192 + ku2*128 + col*4 + tig]
// ku2 0..31 -> W (k = ku2*32 ...), ku2 32..63 -> R.
__global__ void k_pack_bq(const float* __restrict__ W, const float* __restrict__ R) {
    int qid = blockIdx.x * 256 + threadIdx.x;
    if (qid >= NB_ * 8192) return;
    int bk  = qid >> 13;
    int rem = qid & 8191;
    int ku2 = rem >> 7;
    int col = (rem >> 2) & 31;
    int tig = rem & 3;
    int sc = (bk == NUB_) ? col : 32 + (col >> 3) * 1024 + bk * 8 + (col & 7);
    const float* M = (ku2 < 32) ? W : R;
    int kb = (ku2 & 31) * 32 + 2 * tig;
    const float* Mc = M + sc;
    uint4 q;
    q.x = pack2(Mc[(size_t)(kb)      * G_], Mc[(size_t)(kb + 1)  * G_]);
    q.y = pack2(Mc[(size_t)(kb + 8)  * G_], Mc[(size_t)(kb + 9)  * G_]);
    q.z = pack2(Mc[(size_t)(kb + 16) * G_], Mc[(size_t)(kb + 17) * G_]);
    q.w = pack2(Mc[(size_t)(kb + 24) * G_], Mc[(size_t)(kb + 25) * G_]);
    g_bq[qid] = q;
}

__global__ void k_zero() {
    int i = blockIdx.x * blockDim.x + threadIdx.x;
    if (i < 8192) g_hq[0][i] = make_uint4(0u, 0u, 0u, 0u);
    if (i == 0) { g_ctr = 0u; g_mflag = 0u; }
}

// ---------------- fused persistent kernel -------------------------------------
// 129 blocks x 256 threads. z_t = [x_t, h_{t-1}] @ [W;R] + bias, K=2048.
// smem: Bs 8192 uint4 (128KB) | As 2x2048 uint4 (64KB) | zs 2048f | cs 512f | bs 32f
__global__ __launch_bounds__(256, 1) void k_rec(float* __restrict__ out,
                                                const float* __restrict__ bias) {
    extern __shared__ uint4 sm4[];
    uint4* Bs = sm4;               // 8192
    uint4* As = sm4 + 8192;        // 2 x 2048
    float* zs = (float*)(sm4 + 8192 + 4096);  // 64 x 32
    float* cs = zs + 2048;                    // 64 x 8
    float* bs = cs + 512;                     // 32

    const int tid  = threadIdx.x;
    const int bk   = blockIdx.x;
    const int warp = tid >> 5, lane = tid & 31;
    const int grp  = lane >> 2, tig = lane & 3;
    const int bgrp = warp >> 1;                // A row group (rows bgrp*16..)
    const int wN   = (warp & 1) * 16;
    const int u0   = bk * 8;
    const int lvl  = bk >> 3;
    const bool master = (bk == NUB_);

    // one-time: [W;R] frags -> smem, bias, zero cell state
    {
        const uint4* bsrc = g_bq + (size_t)bk * 8192;
        #pragma unroll
        for (int r = 0; r < 32; r++) cp16(Bs + tid + r * 256, bsrc + tid + r * 256);
        cpcommit(); cpwait<0>();
        if (tid < 32) {
            int sc = master ? tid : 32 + (tid >> 3) * 1024 + bk * 8 + (tid & 7);
            bs[tid] = bias[sc];
        }
        for (int i = tid; i < 512; i += 256) cs[i] = 0.f;
        __syncthreads();
    }

    for (int t = 0; t < T_; ++t) {
        const uint4* xsrc = g_xtq + (size_t)t * 8192;
        const uint4* hsrc = g_hq[t & 1];

        // chunks 0,1 (x part — no dependency)
        #pragma unroll
        for (int r = 0; r < 8; r++) cp16(As + tid + r * 256, xsrc + tid + r * 256);
        cpcommit();
        #pragma unroll
        for (int r = 0; r < 8; r++) cp16(As + 2048 + tid + r * 256, xsrc + 2048 + tid + r * 256);
        cpcommit();

        float acc[2][4] = {{0.f,0.f,0.f,0.f},{0.f,0.f,0.f,0.f}};

        #pragma unroll 1
        for (int c = 0; c < 8; ++c) {
            if (c < 7) cpwait<1>(); else cpwait<0>();
            __syncthreads();
            const uint4* A = As + (c & 1) * 2048;
            #pragma unroll
            for (int k = 0; k < 8; ++k) {
                int ku2 = c * 8 + k;
                uint4 aE = A[(2 * k)     * 128 + bgrp * 32 + lane];
                uint4 aO = A[(2 * k + 1) * 128 + bgrp * 32 + lane];
                #pragma unroll
                for (int nt = 0; nt < 2; nt++) {
                    int col = wN + nt * 8 + grp;
                    uint4 bq = Bs[ku2 * 128 + col * 4 + tig];
                    mma_f16(acc[nt], aE.x, aE.y, aE.z, aE.w, bq.x, bq.y);
                    mma_f16(acc[nt], aO.x, aO.y, aO.z, aO.w, bq.z, bq.w);
                }
            }
            // h-ready gate: must pass before issuing chunk 4 (first h chunk)
            if (c == 2 && tid == 0) {
                unsigned target = 129u * (unsigned)t;
                while (*(volatile unsigned*)&g_ctr < target) __nanosleep(32);
            }
            __syncthreads();
            if (c < 6) {
                const uint4* src = (c + 2 < 4) ? (xsrc + (c + 2) * 2048)
                                               : (hsrc + (c - 2) * 2048);
                uint4* dst = As + (c & 1) * 2048;
                #pragma unroll
                for (int r = 0; r < 8; r++) cp16(dst + tid + r * 256, src + tid + r * 256);
                cpcommit();
            }
        }

        // z = acc + bias -> zs
        {
            int wM = bgrp * 16;
            #pragma unroll
            for (int nt = 0; nt < 2; nt++) {
                int c0 = wN + nt * 8 + tig * 2;
                int r0 = wM + grp;
                float bv0 = bs[c0], bv1 = bs[c0 + 1];
                zs[r0 * 32 + c0]           = acc[nt][0] + bv0;
                zs[r0 * 32 + c0 + 1]       = acc[nt][1] + bv1;
                zs[(r0 + 8) * 32 + c0]     = acc[nt][2] + bv0;
                zs[(r0 + 8) * 32 + c0 + 1] = acc[nt][3] + bv1;
            }
        }
        __syncthreads();

        if (master) {
            if (tid < 128) {
                int b = tid >> 1, half = tid & 1;
                float v[16], mx = -1e30f;
                #pragma unroll
                for (int i = 0; i < 16; i++) {
                    v[i] = zs[b * 32 + half * 16 + i];
                    mx = fmaxf(mx, v[i]);
                }
                float s = 0.f;
                #pragma unroll
                for (int i = 0; i < 16; i++) { v[i] = expf(v[i] - mx); s += v[i]; }
                float inv = 1.f / s;
                if (half == 0) {
                    float run = 0.f;
                    #pragma unroll
                    for (int i = 0; i < 16; i++) {
                        run += v[i] * inv;
                        __stcg(&g_masters[b * 32 + i], run);
                    }
                } else {
                    float run = 0.f;
                    #pragma unroll
                    for (int i = 15; i >= 0; i--) {
                        run += v[i] * inv;
                        __stcg(&g_masters[b * 32 + 16 + i], run);
                    }
                }
            }
            __threadfence();
            __syncthreads();
            if (tid == 0) {
                *(volatile unsigned*)&g_mflag = (unsigned)(t + 1);
                atomicAdd(&g_ctr, 1u);
            }
        } else {
            if (tid == 0) {
                while (*(volatile unsigned*)&g_mflag < (unsigned)(t + 1)) __nanosleep(32);
            }
            __syncthreads();
            uint4* hout4 = g_hq[(t + 1) & 1];
            if (tid < 128) {
                int bg = tid >> 5;
                int ln = tid & 31;
                int gp = ln >> 2, tg = ln & 3;
                int r  = bg * 16 + gp;
                int j0 = 2 * tg;
                float fmA = __ldcg(&g_masters[r * 32 + lvl]);
                float imA = __ldcg(&g_masters[r * 32 + 16 + lvl]);
                float fmB = __ldcg(&g_masters[(r + 8) * 32 + lvl]);
                float imB = __ldcg(&g_masters[(r + 8) * 32 + 16 + lvl]);
                float hv[4];
                #pragma unroll
                for (int e = 0; e < 4; e++) {
                    int row = r + ((e >> 1) ? 8 : 0);
                    int j = j0 + (e & 1);
                    float fm = (e >> 1) ? fmB : fmA;
                    float im = (e >> 1) ? imB : imA;
                    float fz = zs[row * 32 + j];
                    float iz = zs[row * 32 + 8 + j];
                    float oz = zs[row * 32 + 16 + j];
                    float gz = zs[row * 32 + 24 + j];
                    float f = 1.f / (1.f + expf(-fz));
                    float i = 1.f / (1.f + expf(-iz));
                    float o = 1.f / (1.f + expf(-oz));
                    float g = tanhf(gz);
                    float cp = cs[row * 8 + j];
                    float w = fm * im;
                    float c = w * (f * cp + i * g) + (fm - w) * cp + (im - w) * g;
                    cs[row * 8 + j] = c;
                    hv[e] = o * tanhf(c);
                }
                // output (b-major), vectorized: (r: j0,j0+1), (r+8: j0,j0+1)
                float2 o0 = make_float2(hv[0], hv[1]);
                float2 o1 = make_float2(hv[2], hv[3]);
                *(float2*)&out[((size_t)r * T_ + t) * U_ + u0 + j0] = o0;
                *(float2*)&out[((size_t)(r + 8) * T_ + t) * U_ + u0 + j0] = o1;
                // h for next step, fp16 A-frag layout
                unsigned w0 = pack2(hv[0], hv[1]);
                unsigned w1 = pack2(hv[2], hv[3]);
                char* dst = (char*)(hout4 + (bk >> 1) * 128 + bg * 32 + ln) + (bk & 1) * 8;
                asm volatile("st.global.cg.v2.u32 [%0], {%1,%2};"
                             :: "l"(dst), "r"(w0), "r"(w1) : "memory");
            }
            __threadfence();
            __syncthreads();
            if (tid == 0) atomicAdd(&g_ctr, 1u);
        }
    }
}

// ---------------- entry -------------------------------------------------------
extern "C" void kernel_launch(void* const* d_in, const int* in_sizes, int n_in,
                              void* d_out, int out_size) {
    const float* x    = (const float*)d_in[0];
    const float* W    = (const float*)d_in[1];
    const float* R    = (const float*)d_in[2];
    const float* bias = (const float*)d_in[3];
    float* out = (float*)d_out;

    cudaFuncSetAttribute(k_rec, cudaFuncAttributeMaxDynamicSharedMemorySize, 207104);

    k_pack_aq<<<(int)(((size_t)T_ * 8192 + 255) / 256), 256>>>(x);
    k_pack_bq<<<(NB_ * 8192 + 255) / 256, 256>>>(W, R);
    k_zero<<<32, 256>>>();
    k_rec<<<NB_, 256, 207104>>>(out, bias);
}